// round 14
// baseline (speedup 1.0000x reference)
#include <cuda_runtime.h>
#include <cuda_fp16.h>
#include <cstdint>

#define DIM   1024
#define SEQ   2048
#define BATCH 2
#define NH    16
#define HD    64
#define MROWS (BATCH*SEQ)   /* 4096 */

/* ------------- scratch (device globals, fp16 packed as u32) -------------- */
__device__ uint32_t g_qt[MROWS*DIM/2];
__device__ uint32_t g_kt[MROWS*DIM/2];
__device__ uint32_t g_vt[MROWS*DIM/2];
__device__ uint32_t g_wq[DIM*DIM/2];
__device__ uint32_t g_wk[DIM*DIM/2];
__device__ uint32_t g_wv[DIM*DIM/2];
__device__ uint32_t g_wo[DIM*DIM/2];
__device__ uint32_t g_qh[BATCH*NH*SEQ*HD/2];  /* [B,H,S,hd/2], Q pre-scaled */
__device__ uint32_t g_kh[BATCH*NH*SEQ*HD/2];
__device__ uint32_t g_vh[BATCH*NH*SEQ*HD/2];
__device__ uint32_t g_ao[MROWS*DIM/2];        /* [B*S, D/2] attn output */

__device__ __forceinline__ uint32_t h2pack(float lo, float hi) {
    __half2 h = __floats2half2_rn(lo, hi);
    return *(uint32_t*)&h;
}
__device__ __forceinline__ float ex2f(float x) {
    float r;
    asm("ex2.approx.ftz.f32 %0, %1;" : "=f"(r) : "f"(x));
    return r;
}
__device__ __forceinline__ uint32_t cvt_f16x2(float hi, float lo) {
    uint32_t r;
    asm("cvt.rn.f16x2.f32 %0, %1, %2;" : "=r"(r) : "f"(hi), "f"(lo));
    return r;
}
__device__ __forceinline__ uint32_t ex2_h2(uint32_t x) {
    uint32_t r;
    asm("ex2.approx.f16x2 %0, %1;" : "=r"(r) : "r"(x));
    return r;
}
__device__ __forceinline__ uint32_t hadd2u(uint32_t a, uint32_t b) {
    uint32_t r;
    asm("add.rn.f16x2 %0, %1, %2;" : "=r"(r) : "r"(a), "r"(b));
    return r;
}

__device__ __forceinline__ void mma_f16(float* d, const uint32_t* a, const uint32_t* b) {
    asm volatile(
        "mma.sync.aligned.m16n8k16.row.col.f32.f16.f16.f32 "
        "{%0,%1,%2,%3}, {%4,%5,%6,%7}, {%8,%9}, {%0,%1,%2,%3};\n"
        : "+f"(d[0]), "+f"(d[1]), "+f"(d[2]), "+f"(d[3])
        : "r"(a[0]), "r"(a[1]), "r"(a[2]), "r"(a[3]), "r"(b[0]), "r"(b[1]));
}

__device__ __forceinline__ void ldsm_x4(uint32_t& r0, uint32_t& r1,
                                        uint32_t& r2, uint32_t& r3, uint32_t addr) {
    asm volatile("ldmatrix.sync.aligned.m8n8.x4.shared.b16 {%0,%1,%2,%3}, [%4];"
                 : "=r"(r0), "=r"(r1), "=r"(r2), "=r"(r3) : "r"(addr));
}

__device__ __forceinline__ void cp16(uint32_t* smem_dst, const uint32_t* gsrc) {
    uint32_t sa = (uint32_t)__cvta_generic_to_shared(smem_dst);
    asm volatile("cp.async.cg.shared.global [%0], [%1], 16;"
                 :: "r"(sa), "l"(gsrc) : "memory");
}
#define CP_COMMIT() asm volatile("cp.async.commit_group;" ::: "memory")
#define CP_WAIT(n)  asm volatile("cp.async.wait_group %0;" :: "n"(n) : "memory")

/* xor swizzle for 32-u32 (64-half) rows: 16B-aligned, conflict-free        */
#define SWZ32(row, c) ((row) * 32 + ((c) ^ (((row) & 7) << 2)))

/* ------------------- fused fp32 -> fp16 convert --------------------------- */
__global__ __launch_bounds__(256) void cvt_all_kernel(
    const float* __restrict__ s0, const float* __restrict__ s1,
    const float* __restrict__ s2, const float* __restrict__ s3,
    const float* __restrict__ s4, const float* __restrict__ s5,
    const float* __restrict__ s6,
    uint32_t* __restrict__ d0, uint32_t* __restrict__ d1,
    uint32_t* __restrict__ d2, uint32_t* __restrict__ d3,
    uint32_t* __restrict__ d4, uint32_t* __restrict__ d5,
    uint32_t* __restrict__ d6)
{
    const float* srcs[7] = { s0, s1, s2, s3, s4, s5, s6 };
    uint32_t*    dsts[7] = { d0, d1, d2, d3, d4, d5, d6 };
    const int ns[7] = { MROWS*DIM/4, MROWS*DIM/4, MROWS*DIM/4,
                        DIM*DIM/4, DIM*DIM/4, DIM*DIM/4, DIM*DIM/4 };
    const int t = blockIdx.y;
    const int i = blockIdx.x * 256 + threadIdx.x;
    if (i < ns[t]) {
        float4 v = *(const float4*)(srcs[t] + (size_t)i * 4);
        uint2 o = make_uint2(h2pack(v.x, v.y), h2pack(v.z, v.w));
        *(uint2*)(dsts[t] + (size_t)i * 2) = o;
    }
}

/* =================== fp16 GEMM: C = A @ W^T (frozen R11) ================== */
#define BM 128
#define BN 128
#define NKT 16
#define ROWU 32
#define A_U32 (BM * ROWU)           /* 4096 */
#define B_U32 (BN * ROWU)           /* 4096 */
#define STG_U32 (A_U32 + B_U32)     /* 8192 */
#define NSTAGE 3
#define GEMM_SMEM (NSTAGE * STG_U32 * 4)  /* 98304 B */
#define GSTRIDE (DIM / 2)

__device__ __forceinline__ void stage_async(
    uint32_t* __restrict__ As, uint32_t* __restrict__ Bs,
    const uint32_t* __restrict__ A, const uint32_t* __restrict__ W,
    int m0, int n0, int kc, int tid)
{
#pragma unroll
    for (int i = 0; i < 4; i++) {
        int f = tid + (i << 8);
        int row = f >> 3, c4 = (f & 7) << 2;
        cp16(As + SWZ32(row, c4), A + (size_t)(m0 + row) * GSTRIDE + kc + c4);
    }
#pragma unroll
    for (int i = 0; i < 4; i++) {
        int f = tid + (i << 8);
        int row = f >> 3, c4 = (f & 7) << 2;
        cp16(Bs + SWZ32(row, c4), W + (size_t)(n0 + row) * GSTRIDE + kc + c4);
    }
}

__device__ __forceinline__ void gemm_body(
    const uint32_t* __restrict__ A, const uint32_t* __restrict__ W,
    float* __restrict__ Cf, uint32_t* __restrict__ Ch, int mode, float scale)
{
    extern __shared__ uint32_t smg[];

    const int tid  = threadIdx.x;
    const int lane = tid & 31;
    const int wid  = tid >> 5;
    const int wm0  = (wid >> 2) << 6;
    const int wn0  = (wid & 3) << 5;
    const int m0   = blockIdx.y * BM;
    const int n0   = blockIdx.x * BN;
    const int r0   = lane >> 2;
    const int tig  = lane & 3;

    const int lgrp = lane >> 3, lrow = lane & 7;
    const int a_roff = ((lgrp & 1) << 3) + lrow, a_coff = (lgrp >> 1) << 2;
    const int b_roff = ((lgrp >> 1) << 3) + lrow, b_coff = (lgrp & 1) << 2;

    const uint32_t sb = (uint32_t)__cvta_generic_to_shared(smg);

    float acc[4][4][4];
#pragma unroll
    for (int mt = 0; mt < 4; mt++)
#pragma unroll
        for (int nt = 0; nt < 4; nt++)
#pragma unroll
            for (int e = 0; e < 4; e++) acc[mt][nt][e] = 0.f;

#pragma unroll
    for (int p = 0; p < NSTAGE - 1; p++) {
        stage_async(smg + p * STG_U32, smg + p * STG_U32 + A_U32,
                    A, W, m0, n0, p * ROWU, tid);
        CP_COMMIT();
    }

    for (int kt = 0; kt < NKT; kt++) {
        CP_WAIT(NSTAGE - 2);
        __syncthreads();

        if (kt + NSTAGE - 1 < NKT) {
            const int w = (kt + NSTAGE - 1) % NSTAGE;
            stage_async(smg + w * STG_U32, smg + w * STG_U32 + A_U32,
                        A, W, m0, n0, (kt + NSTAGE - 1) * ROWU, tid);
        }
        CP_COMMIT();

        const uint32_t abase = sb + (uint32_t)((kt % NSTAGE) * STG_U32) * 4u;
        const uint32_t bbase = abase + A_U32 * 4u;
#pragma unroll
        for (int ks = 0; ks < 4; ks++) {
            const int c0 = ks << 3;
            uint32_t af[4][4], bf[4][2];
#pragma unroll
            for (int mt = 0; mt < 4; mt++) {
                int row = wm0 + (mt << 4) + a_roff;
                ldsm_x4(af[mt][0], af[mt][1], af[mt][2], af[mt][3],
                        abase + 4u * (uint32_t)SWZ32(row, c0 + a_coff));
            }
#pragma unroll
            for (int p2 = 0; p2 < 2; p2++) {
                int n = wn0 + (p2 << 4) + b_roff;
                ldsm_x4(bf[2*p2][0], bf[2*p2][1], bf[2*p2+1][0], bf[2*p2+1][1],
                        bbase + 4u * (uint32_t)SWZ32(n, c0 + b_coff));
            }
#pragma unroll
            for (int mt = 0; mt < 4; mt++)
#pragma unroll
                for (int nt = 0; nt < 4; nt++)
                    mma_f16(acc[mt][nt], af[mt], bf[nt]);
        }
    }

#pragma unroll
    for (int mt = 0; mt < 4; mt++) {
#pragma unroll
        for (int half = 0; half < 2; half++) {
            const int m = m0 + wm0 + (mt << 4) + r0 + (half << 3);
            if (mode == 1) {
                const int b = m >> 11, srow = m & (SEQ - 1);
#pragma unroll
                for (int nt = 0; nt < 4; nt++) {
                    int col = n0 + wn0 + (nt << 3) + (tig << 1);
                    int h = col >> 6, dd = col & 63;
                    uint32_t val = h2pack(acc[mt][nt][half * 2]     * scale,
                                          acc[mt][nt][half * 2 + 1] * scale);
                    Ch[((size_t)((b * NH + h) * SEQ + srow) << 5) + (dd >> 1)] = val;
                }
            } else {
#pragma unroll
                for (int nt = 0; nt < 4; nt++) {
                    int col = n0 + wn0 + (nt << 3) + (tig << 1);
                    float2 val = make_float2(acc[mt][nt][half * 2],
                                             acc[mt][nt][half * 2 + 1]);
                    *(float2*)(Cf + (size_t)m * DIM + col) = val;
                }
            }
        }
    }
}

__global__ __launch_bounds__(256, 2) void gemm_qkv(
    const uint32_t* __restrict__ qt, const uint32_t* __restrict__ kt_,
    const uint32_t* __restrict__ vt, const uint32_t* __restrict__ wq,
    const uint32_t* __restrict__ wk, const uint32_t* __restrict__ wv,
    uint32_t* __restrict__ qh, uint32_t* __restrict__ kh, uint32_t* __restrict__ vh)
{
    const uint32_t* A; const uint32_t* W; uint32_t* C; float scale;
    if (blockIdx.z == 0)      { A = qt;  W = wq; C = qh; scale = 0.125f * 1.44269504f; }
    else if (blockIdx.z == 1) { A = kt_; W = wk; C = kh; scale = 1.0f; }
    else                      { A = vt;  W = wv; C = vh; scale = 1.0f; }
    gemm_body(A, W, nullptr, C, 1, scale);
}

__global__ __launch_bounds__(256, 2) void gemm_out(
    const uint32_t* __restrict__ A, const uint32_t* __restrict__ W,
    float* __restrict__ C)
{
    gemm_body(A, W, C, nullptr, 0, 1.0f);
}

/* ============ fp16 flash attention: Q=128 rows, 8 warps x 16 rows =========
   Halved per-warp register state (~130 regs) -> 2 CTA/SM, no spills.
   3-stage K/V, distance-2 prefetch.  SMEM = 64 KB.                         */
#define FQ   4096
#define FKV  2048

__global__ __launch_bounds__(256, 2) void flash_attn(
    const uint32_t* __restrict__ Qh, const uint32_t* __restrict__ Kh,
    const uint32_t* __restrict__ Vh, uint32_t* __restrict__ AO)
{
    extern __shared__ uint32_t fsm[];
    uint32_t* Qs = fsm;
    uint32_t* Ksb[3] = { fsm + FQ,         fsm + FQ + FKV,   fsm + FQ + 2*FKV };
    uint32_t* Vsb[3] = { fsm + FQ + 3*FKV, fsm + FQ + 4*FKV, fsm + FQ + 5*FKV };

    const int bh = blockIdx.y;
    const int qt = gridDim.x - 1 - blockIdx.x;    /* heavy tiles first */
    const int q0 = qt * 128;
    const uint32_t* Qb = Qh + (size_t)bh * SEQ * (HD/2);
    const uint32_t* Kb = Kh + (size_t)bh * SEQ * (HD/2);
    const uint32_t* Vb = Vh + (size_t)bh * SEQ * (HD/2);

    const int tid  = threadIdx.x;
    const int lane = tid & 31;
    const int wid  = tid >> 5;           /* 0..7 */
    const int r0   = lane >> 2;
    const int tig  = lane & 3;
    const int wq   = wid << 4;           /* 16 q-rows per warp */

    const int lgrp = lane >> 3, lrow = lane & 7;
    const int b_roff = ((lgrp >> 1) << 3) + lrow, b_coff = (lgrp & 1) << 2;
    const int lm_key = ((lgrp & 1) << 3) + lrow;
    const int lm_nt2 = lgrp >> 1;

    const int nkt = 2 * qt + 2;

    /* group 0: Q tile (4096 u32, 256 thr x 4 cp16) */
#pragma unroll
    for (int i = 0; i < 4; i++) {
        int f = tid + (i << 8);
        int row = f >> 3, c4 = (f & 7) << 2;
        cp16(Qs + SWZ32(row, c4), Qb + (size_t)(q0 + row) * (HD/2) + c4);
    }
    CP_COMMIT();
    /* groups 1,2: K/V tiles 0 and 1 */
#pragma unroll
    for (int p = 0; p < 2; p++) {
        if (p < nkt) {
#pragma unroll
            for (int i = 0; i < 2; i++) {
                int f = tid + (i << 8);
                int row = f >> 3, c4 = (f & 7) << 2;
                cp16(Ksb[p] + SWZ32(row, c4),
                     Kb + (size_t)(p * 64 + row) * (HD/2) + c4);
            }
#pragma unroll
            for (int i = 0; i < 2; i++) {
                int f = tid + (i << 8);
                int row = f >> 3, c4 = (f & 7) << 2;
                cp16(Vsb[p] + SWZ32(row, c4),
                     Vb + (size_t)(p * 64 + row) * (HD/2) + c4);
            }
        }
        CP_COMMIT();
    }

    CP_WAIT(2);            /* Q resident; K/V[0],K/V[1] may be in flight */
    __syncthreads();

    /* Q fragments to registers: 4 k-steps x 4 regs (16-row A fragments) */
    uint32_t qf[4][4];
#pragma unroll
    for (int ks = 0; ks < 4; ks++) {
        const int kb = (ks << 3) + tig;
        const int row = wq + r0;
        qf[ks][0] = Qs[SWZ32(row,     kb)];
        qf[ks][1] = Qs[SWZ32(row + 8, kb)];
        qf[ks][2] = Qs[SWZ32(row,     kb + 4)];
        qf[ks][3] = Qs[SWZ32(row + 8, kb + 4)];
    }

    float o[8][4];
    float mi[2], li[2];
#pragma unroll
    for (int i = 0; i < 2; i++) { mi[i] = -1e30f; li[i] = 0.f; }
#pragma unroll
    for (int nt = 0; nt < 8; nt++)
#pragma unroll
        for (int e = 0; e < 4; e++) o[nt][e] = 0.f;

    for (int kt = 0; kt < nkt; kt++) {
        const int k0 = kt << 6;

        CP_WAIT(1);           /* K/V[kt] resident */
        __syncthreads();

        /* prefetch K/V[kt+2] (distance 2) — overlaps compute below */
        if (kt + 2 < nkt) {
            const uint32_t* Kp = Kb + (size_t)(k0 + 128) * (HD/2);
            const uint32_t* Vp = Vb + (size_t)(k0 + 128) * (HD/2);
            uint32_t* Kd = Ksb[(kt + 2) % 3];
            uint32_t* Vd = Vsb[(kt + 2) % 3];
#pragma unroll
            for (int i = 0; i < 2; i++) {
                int f = tid + (i << 8);
                int row = f >> 3, c4 = (f & 7) << 2;
                cp16(Kd + SWZ32(row, c4), Kp + (size_t)row * (HD/2) + c4);
            }
#pragma unroll
            for (int i = 0; i < 2; i++) {
                int f = tid + (i << 8);
                int row = f >> 3, c4 = (f & 7) << 2;
                cp16(Vd + SWZ32(row, c4), Vp + (size_t)row * (HD/2) + c4);
            }
        }
        CP_COMMIT();          /* always commit — keeps group counts aligned */

        const uint32_t kbase = (uint32_t)__cvta_generic_to_shared(Ksb[kt % 3]);
        const uint32_t vbase = (uint32_t)__cvta_generic_to_shared(Vsb[kt % 3]);
        const bool active = (k0 <= q0 + wq + 15);
        if (active) {
            /* S = Q K^T for this warp's 16 rows x 64 keys */
            float s[8][4];
#pragma unroll
            for (int nt = 0; nt < 8; nt++)
#pragma unroll
                for (int e = 0; e < 4; e++) s[nt][e] = 0.f;

#pragma unroll
            for (int ks = 0; ks < 4; ks++) {
                const int c0 = ks << 3;
                uint32_t bf[8][2];
#pragma unroll
                for (int p2 = 0; p2 < 4; p2++) {
                    int n = (p2 << 4) + b_roff;
                    ldsm_x4(bf[2*p2][0], bf[2*p2][1], bf[2*p2+1][0], bf[2*p2+1][1],
                            kbase + 4u * (uint32_t)SWZ32(n, c0 + b_coff));
                }
#pragma unroll
                for (int nt = 0; nt < 8; nt++)
                    mma_f16(s[nt], qf[ks], bf[nt]);
            }

            /* causal mask near diagonal */
            if (k0 + 63 > q0 + wq) {
#pragma unroll
                for (int nt = 0; nt < 8; nt++)
#pragma unroll
                    for (int e = 0; e < 4; e++) {
                        int rg = q0 + wq + ((e >> 1) << 3) + r0;
                        int cg = k0 + (nt << 3) + (tig << 1) + (e & 1);
                        if (cg > rg) s[nt][e] = -1e30f;
                    }
            }

            /* online softmax (base-2); P packed to f16x2 in regs */
            uint32_t pk[8][2];
#pragma unroll
            for (int half = 0; half < 2; half++) {
                float mx = -1e30f;
#pragma unroll
                for (int nt = 0; nt < 8; nt++)
                    mx = fmaxf(mx, fmaxf(s[nt][half*2], s[nt][half*2+1]));
                mx = fmaxf(mx, __shfl_xor_sync(0xffffffffu, mx, 1));
                mx = fmaxf(mx, __shfl_xor_sync(0xffffffffu, mx, 2));
                float mnew = fmaxf(mi[half], mx);
                float corr = ex2f(mi[half] - mnew);
                uint32_t sA = 0, sB = 0;
#pragma unroll
                for (int nt = 0; nt < 8; nt++) {
                    float x0 = s[nt][half*2]     - mnew;
                    float x1 = s[nt][half*2 + 1] - mnew;
                    uint32_t pe = ex2_h2(cvt_f16x2(x1, x0));
                    pk[nt][half] = pe;
                    if (nt & 1) sB = hadd2u(sB, pe); else sA = hadd2u(sA, pe);
                }
                float2 sf = __half22float2(*(__half2*)&(sA = hadd2u(sA, sB)));
                float sum = sf.x + sf.y;
                sum += __shfl_xor_sync(0xffffffffu, sum, 1);
                sum += __shfl_xor_sync(0xffffffffu, sum, 2);
                li[half] = li[half] * corr + sum;
                mi[half] = mnew;
#pragma unroll
                for (int nt = 0; nt < 8; nt++) {
                    o[nt][half*2]     *= corr;
                    o[nt][half*2 + 1] *= corr;
                }
            }

            /* O += P V */
#pragma unroll
            for (int ks = 0; ks < 4; ks++) {
                uint32_t bf[8][2];
#pragma unroll
                for (int j = 0; j < 4; j++) {
                    int key = (ks << 4) + lm_key;
                    int c   = ((j << 1) + lm_nt2) << 2;
                    uint32_t t0, t1, t2, t3;
                    asm volatile(
                        "ldmatrix.sync.aligned.m8n8.x4.trans.shared.b16 "
                        "{%0,%1,%2,%3}, [%4];"
                        : "=r"(t0), "=r"(t1), "=r"(t2), "=r"(t3)
                        : "r"(vbase + 4u * (uint32_t)SWZ32(key, c)));
                    bf[(j << 1)    ][0] = t0;
                    bf[(j << 1)    ][1] = t1;
                    bf[(j << 1) + 1][0] = t2;
                    bf[(j << 1) + 1][1] = t3;
                }
                uint32_t af[4] = { pk[2*ks][0], pk[2*ks][1],
                                   pk[2*ks+1][0], pk[2*ks+1][1] };
#pragma unroll
                for (int nt = 0; nt < 8; nt++)
                    mma_f16(o[nt], af, bf[nt]);
            }
        }
    }

    /* epilogue: normalize, store packed fp16 into AO */
    const int b = bh >> 4, h = bh & 15;
#pragma unroll
    for (int half = 0; half < 2; half++) {
        const float inv = 1.f / li[half];
        const int rg = q0 + wq + (half << 3) + r0;
        uint32_t* row = AO + (size_t)(b * SEQ + rg) * GSTRIDE + (h << 5);
#pragma unroll
        for (int nt = 0; nt < 8; nt++) {
            row[(nt << 2) + tig] = h2pack(o[nt][half*2]     * inv,
                                          o[nt][half*2 + 1] * inv);
        }
    }
}

/* ---------------- launch -------------------------------------------------- */
extern "C" void kernel_launch(void* const* d_in, const int* in_sizes, int n_in,
                              void* d_out, int out_size)
{
    const float* q  = (const float*)d_in[0];
    const float* k  = (const float*)d_in[1];
    const float* v  = (const float*)d_in[2];
    const float* wq = (const float*)d_in[3];
    const float* wk = (const float*)d_in[4];
    const float* wv = (const float*)d_in[5];
    const float* wo = (const float*)d_in[6];

    uint32_t *qt, *kt, *vt, *wqt, *wkt, *wvt, *wot, *qh, *kh, *vh, *ao;
    cudaGetSymbolAddress((void**)&qt,  g_qt);
    cudaGetSymbolAddress((void**)&kt,  g_kt);
    cudaGetSymbolAddress((void**)&vt,  g_vt);
    cudaGetSymbolAddress((void**)&wqt, g_wq);
    cudaGetSymbolAddress((void**)&wkt, g_wk);
    cudaGetSymbolAddress((void**)&wvt, g_wv);
    cudaGetSymbolAddress((void**)&wot, g_wo);
    cudaGetSymbolAddress((void**)&qh,  g_qh);
    cudaGetSymbolAddress((void**)&kh,  g_kh);
    cudaGetSymbolAddress((void**)&vh,  g_vh);
    cudaGetSymbolAddress((void**)&ao,  g_ao);

    const int flash_smem = (FQ + 6 * FKV) * 4;   /* 65536 */
    cudaFuncSetAttribute(gemm_qkv,  cudaFuncAttributeMaxDynamicSharedMemorySize, GEMM_SMEM);
    cudaFuncSetAttribute(gemm_out,  cudaFuncAttributeMaxDynamicSharedMemorySize, GEMM_SMEM);
    cudaFuncSetAttribute(flash_attn, cudaFuncAttributeMaxDynamicSharedMemorySize, flash_smem);

    dim3 gcvt(MROWS * DIM / 4 / 256, 7);     /* 4096 x 7 */
    cvt_all_kernel<<<gcvt, 256>>>(q, k, v, wq, wk, wv, wo,
                                  qt, kt, vt, wqt, wkt, wvt, wot);

    dim3 gqkv(DIM / BN, MROWS / BM, 3);        /* 8 x 32 x 3 */
    gemm_qkv<<<gqkv, 256, GEMM_SMEM>>>(qt, kt, vt, wqt, wkt, wvt, qh, kh, vh);

    flash_attn<<<dim3(SEQ / 128, BATCH * NH), 256, flash_smem>>>(qh, kh, vh, ao);

    dim3 gout(DIM / BN, MROWS / BM);           /* 8 x 32 */
    gemm_out<<<gout, 256, GEMM_SMEM>>>(ao, wot, (float*)d_out);
}

// round 15
// speedup vs baseline: 1.0288x; 1.0288x over previous
#include <cuda_runtime.h>
#include <cuda_fp16.h>
#include <cstdint>

#define DIM   1024
#define SEQ   2048
#define BATCH 2
#define NH    16
#define HD    64
#define MROWS (BATCH*SEQ)   /* 4096 */

/* ------------- scratch (device globals, fp16 packed as u32) -------------- */
__device__ uint32_t g_qt[MROWS*DIM/2];
__device__ uint32_t g_kt[MROWS*DIM/2];
__device__ uint32_t g_vt[MROWS*DIM/2];
__device__ uint32_t g_wq[DIM*DIM/2];
__device__ uint32_t g_wk[DIM*DIM/2];
__device__ uint32_t g_wv[DIM*DIM/2];
__device__ uint32_t g_wo[DIM*DIM/2];
__device__ uint32_t g_qh[BATCH*NH*SEQ*HD/2];  /* [B,H,S,hd/2], Q pre-scaled */
__device__ uint32_t g_kh[BATCH*NH*SEQ*HD/2];
__device__ uint32_t g_vh[BATCH*NH*SEQ*HD/2];
__device__ uint32_t g_ao[MROWS*DIM/2];        /* [B*S, D/2] attn output */

__device__ __forceinline__ uint32_t h2pack(float lo, float hi) {
    __half2 h = __floats2half2_rn(lo, hi);
    return *(uint32_t*)&h;
}
__device__ __forceinline__ float ex2f(float x) {
    float r;
    asm("ex2.approx.ftz.f32 %0, %1;" : "=f"(r) : "f"(x));
    return r;
}
__device__ __forceinline__ uint32_t cvt_f16x2(float hi, float lo) {
    uint32_t r;
    asm("cvt.rn.f16x2.f32 %0, %1, %2;" : "=r"(r) : "f"(hi), "f"(lo));
    return r;
}
__device__ __forceinline__ uint32_t ex2_h2(uint32_t x) {
    uint32_t r;
    asm("ex2.approx.f16x2 %0, %1;" : "=r"(r) : "r"(x));
    return r;
}
__device__ __forceinline__ uint32_t hadd2u(uint32_t a, uint32_t b) {
    uint32_t r;
    asm("add.rn.f16x2 %0, %1, %2;" : "=r"(r) : "r"(a), "r"(b));
    return r;
}

__device__ __forceinline__ void mma_f16(float* d, const uint32_t* a, const uint32_t* b) {
    asm volatile(
        "mma.sync.aligned.m16n8k16.row.col.f32.f16.f16.f32 "
        "{%0,%1,%2,%3}, {%4,%5,%6,%7}, {%8,%9}, {%0,%1,%2,%3};\n"
        : "+f"(d[0]), "+f"(d[1]), "+f"(d[2]), "+f"(d[3])
        : "r"(a[0]), "r"(a[1]), "r"(a[2]), "r"(a[3]), "r"(b[0]), "r"(b[1]));
}

__device__ __forceinline__ void ldsm_x4(uint32_t& r0, uint32_t& r1,
                                        uint32_t& r2, uint32_t& r3, uint32_t addr) {
    asm volatile("ldmatrix.sync.aligned.m8n8.x4.shared.b16 {%0,%1,%2,%3}, [%4];"
                 : "=r"(r0), "=r"(r1), "=r"(r2), "=r"(r3) : "r"(addr));
}

__device__ __forceinline__ void cp16(uint32_t* smem_dst, const uint32_t* gsrc) {
    uint32_t sa = (uint32_t)__cvta_generic_to_shared(smem_dst);
    asm volatile("cp.async.cg.shared.global [%0], [%1], 16;"
                 :: "r"(sa), "l"(gsrc) : "memory");
}
#define CP_COMMIT() asm volatile("cp.async.commit_group;" ::: "memory")
#define CP_WAIT(n)  asm volatile("cp.async.wait_group %0;" :: "n"(n) : "memory")

/* xor swizzle for 32-u32 (64-half) rows: 16B-aligned, conflict-free        */
#define SWZ32(row, c) ((row) * 32 + ((c) ^ (((row) & 7) << 2)))

/* ------------------- fused fp32 -> fp16 convert --------------------------- */
__global__ __launch_bounds__(256) void cvt_all_kernel(
    const float* __restrict__ s0, const float* __restrict__ s1,
    const float* __restrict__ s2, const float* __restrict__ s3,
    const float* __restrict__ s4, const float* __restrict__ s5,
    const float* __restrict__ s6,
    uint32_t* __restrict__ d0, uint32_t* __restrict__ d1,
    uint32_t* __restrict__ d2, uint32_t* __restrict__ d3,
    uint32_t* __restrict__ d4, uint32_t* __restrict__ d5,
    uint32_t* __restrict__ d6)
{
    const float* srcs[7] = { s0, s1, s2, s3, s4, s5, s6 };
    uint32_t*    dsts[7] = { d0, d1, d2, d3, d4, d5, d6 };
    const int ns[7] = { MROWS*DIM/4, MROWS*DIM/4, MROWS*DIM/4,
                        DIM*DIM/4, DIM*DIM/4, DIM*DIM/4, DIM*DIM/4 };
    const int t = blockIdx.y;
    const int i = blockIdx.x * 256 + threadIdx.x;
    if (i < ns[t]) {
        float4 v = *(const float4*)(srcs[t] + (size_t)i * 4);
        uint2 o = make_uint2(h2pack(v.x, v.y), h2pack(v.z, v.w));
        *(uint2*)(dsts[t] + (size_t)i * 2) = o;
    }
}

/* =================== fp16 GEMM: C = A @ W^T (frozen R11) ================== */
#define BM 128
#define BN 128
#define NKT 16
#define ROWU 32
#define A_U32 (BM * ROWU)           /* 4096 */
#define B_U32 (BN * ROWU)           /* 4096 */
#define STG_U32 (A_U32 + B_U32)     /* 8192 */
#define NSTAGE 3
#define GEMM_SMEM (NSTAGE * STG_U32 * 4)  /* 98304 B */
#define GSTRIDE (DIM / 2)

__device__ __forceinline__ void stage_async(
    uint32_t* __restrict__ As, uint32_t* __restrict__ Bs,
    const uint32_t* __restrict__ A, const uint32_t* __restrict__ W,
    int m0, int n0, int kc, int tid)
{
#pragma unroll
    for (int i = 0; i < 4; i++) {
        int f = tid + (i << 8);
        int row = f >> 3, c4 = (f & 7) << 2;
        cp16(As + SWZ32(row, c4), A + (size_t)(m0 + row) * GSTRIDE + kc + c4);
    }
#pragma unroll
    for (int i = 0; i < 4; i++) {
        int f = tid + (i << 8);
        int row = f >> 3, c4 = (f & 7) << 2;
        cp16(Bs + SWZ32(row, c4), W + (size_t)(n0 + row) * GSTRIDE + kc + c4);
    }
}

__device__ __forceinline__ void gemm_body(
    const uint32_t* __restrict__ A, const uint32_t* __restrict__ W,
    float* __restrict__ Cf, uint32_t* __restrict__ Ch, int mode, float scale)
{
    extern __shared__ uint32_t smg[];

    const int tid  = threadIdx.x;
    const int lane = tid & 31;
    const int wid  = tid >> 5;
    const int wm0  = (wid >> 2) << 6;
    const int wn0  = (wid & 3) << 5;
    const int m0   = blockIdx.y * BM;
    const int n0   = blockIdx.x * BN;
    const int r0   = lane >> 2;
    const int tig  = lane & 3;

    const int lgrp = lane >> 3, lrow = lane & 7;
    const int a_roff = ((lgrp & 1) << 3) + lrow, a_coff = (lgrp >> 1) << 2;
    const int b_roff = ((lgrp >> 1) << 3) + lrow, b_coff = (lgrp & 1) << 2;

    const uint32_t sb = (uint32_t)__cvta_generic_to_shared(smg);

    float acc[4][4][4];
#pragma unroll
    for (int mt = 0; mt < 4; mt++)
#pragma unroll
        for (int nt = 0; nt < 4; nt++)
#pragma unroll
            for (int e = 0; e < 4; e++) acc[mt][nt][e] = 0.f;

#pragma unroll
    for (int p = 0; p < NSTAGE - 1; p++) {
        stage_async(smg + p * STG_U32, smg + p * STG_U32 + A_U32,
                    A, W, m0, n0, p * ROWU, tid);
        CP_COMMIT();
    }

    for (int kt = 0; kt < NKT; kt++) {
        CP_WAIT(NSTAGE - 2);
        __syncthreads();

        if (kt + NSTAGE - 1 < NKT) {
            const int w = (kt + NSTAGE - 1) % NSTAGE;
            stage_async(smg + w * STG_U32, smg + w * STG_U32 + A_U32,
                        A, W, m0, n0, (kt + NSTAGE - 1) * ROWU, tid);
        }
        CP_COMMIT();

        const uint32_t abase = sb + (uint32_t)((kt % NSTAGE) * STG_U32) * 4u;
        const uint32_t bbase = abase + A_U32 * 4u;
#pragma unroll
        for (int ks = 0; ks < 4; ks++) {
            const int c0 = ks << 3;
            uint32_t af[4][4], bf[4][2];
#pragma unroll
            for (int mt = 0; mt < 4; mt++) {
                int row = wm0 + (mt << 4) + a_roff;
                ldsm_x4(af[mt][0], af[mt][1], af[mt][2], af[mt][3],
                        abase + 4u * (uint32_t)SWZ32(row, c0 + a_coff));
            }
#pragma unroll
            for (int p2 = 0; p2 < 2; p2++) {
                int n = wn0 + (p2 << 4) + b_roff;
                ldsm_x4(bf[2*p2][0], bf[2*p2][1], bf[2*p2+1][0], bf[2*p2+1][1],
                        bbase + 4u * (uint32_t)SWZ32(n, c0 + b_coff));
            }
#pragma unroll
            for (int mt = 0; mt < 4; mt++)
#pragma unroll
                for (int nt = 0; nt < 4; nt++)
                    mma_f16(acc[mt][nt], af[mt], bf[nt]);
        }
    }

#pragma unroll
    for (int mt = 0; mt < 4; mt++) {
#pragma unroll
        for (int half = 0; half < 2; half++) {
            const int m = m0 + wm0 + (mt << 4) + r0 + (half << 3);
            if (mode == 1) {
                const int b = m >> 11, srow = m & (SEQ - 1);
#pragma unroll
                for (int nt = 0; nt < 4; nt++) {
                    int col = n0 + wn0 + (nt << 3) + (tig << 1);
                    int h = col >> 6, dd = col & 63;
                    uint32_t val = h2pack(acc[mt][nt][half * 2]     * scale,
                                          acc[mt][nt][half * 2 + 1] * scale);
                    Ch[((size_t)((b * NH + h) * SEQ + srow) << 5) + (dd >> 1)] = val;
                }
            } else {
#pragma unroll
                for (int nt = 0; nt < 4; nt++) {
                    int col = n0 + wn0 + (nt << 3) + (tig << 1);
                    float2 val = make_float2(acc[mt][nt][half * 2],
                                             acc[mt][nt][half * 2 + 1]);
                    *(float2*)(Cf + (size_t)m * DIM + col) = val;
                }
            }
        }
    }
}

__global__ __launch_bounds__(256, 2) void gemm_qkv(
    const uint32_t* __restrict__ qt, const uint32_t* __restrict__ kt_,
    const uint32_t* __restrict__ vt, const uint32_t* __restrict__ wq,
    const uint32_t* __restrict__ wk, const uint32_t* __restrict__ wv,
    uint32_t* __restrict__ qh, uint32_t* __restrict__ kh, uint32_t* __restrict__ vh)
{
    const uint32_t* A; const uint32_t* W; uint32_t* C; float scale;
    if (blockIdx.z == 0)      { A = qt;  W = wq; C = qh; scale = 0.125f * 1.44269504f; }
    else if (blockIdx.z == 1) { A = kt_; W = wk; C = kh; scale = 1.0f; }
    else                      { A = vt;  W = wv; C = vh; scale = 1.0f; }
    gemm_body(A, W, nullptr, C, 1, scale);
}

__global__ __launch_bounds__(256, 2) void gemm_out(
    const uint32_t* __restrict__ A, const uint32_t* __restrict__ W,
    float* __restrict__ C)
{
    gemm_body(A, W, C, nullptr, 0, 1.0f);
}

/* ============ fp16 flash attention: Q=128 rows, KEY TILE = 128 ============
   8 warps x 16 q-rows; one softmax pass per 128 keys (fixed costs halved);
   triple-buffered 128-key K/V, distance-2 prefetch.  SMEM = 112 KB.        */
#define FQ    4096
#define FKV2  4096    /* 128 keys x 32 u32 */

__global__ __launch_bounds__(256) void flash_attn(
    const uint32_t* __restrict__ Qh, const uint32_t* __restrict__ Kh,
    const uint32_t* __restrict__ Vh, uint32_t* __restrict__ AO)
{
    extern __shared__ uint32_t fsm[];
    uint32_t* Qs = fsm;
    uint32_t* Ksb[3] = { fsm + FQ,          fsm + FQ + FKV2,   fsm + FQ + 2*FKV2 };
    uint32_t* Vsb[3] = { fsm + FQ + 3*FKV2, fsm + FQ + 4*FKV2, fsm + FQ + 5*FKV2 };

    const int bh = blockIdx.y;
    const int qtile = gridDim.x - 1 - blockIdx.x;   /* heavy tiles first */
    const int q0 = qtile * 128;
    const uint32_t* Qb = Qh + (size_t)bh * SEQ * (HD/2);
    const uint32_t* Kb = Kh + (size_t)bh * SEQ * (HD/2);
    const uint32_t* Vb = Vh + (size_t)bh * SEQ * (HD/2);

    const int tid  = threadIdx.x;
    const int lane = tid & 31;
    const int wid  = tid >> 5;           /* 0..7 */
    const int r0   = lane >> 2;
    const int tig  = lane & 3;
    const int wq   = wid << 4;           /* 16 q-rows per warp */

    const int lgrp = lane >> 3, lrow = lane & 7;
    const int b_roff = ((lgrp >> 1) << 3) + lrow, b_coff = (lgrp & 1) << 2;
    const int lm_key = ((lgrp & 1) << 3) + lrow;
    const int lm_nt2 = lgrp >> 1;

    const int nkt = qtile + 1;           /* 128-key tiles */

    /* group 0: Q tile (4096 u32, 256 thr x 4 cp16) */
#pragma unroll
    for (int i = 0; i < 4; i++) {
        int f = tid + (i << 8);
        int row = f >> 3, c4 = (f & 7) << 2;
        cp16(Qs + SWZ32(row, c4), Qb + (size_t)(q0 + row) * (HD/2) + c4);
    }
    CP_COMMIT();
    /* groups 1,2: K/V tiles 0 and 1 (128 keys each) */
#pragma unroll
    for (int p = 0; p < 2; p++) {
        if (p < nkt) {
#pragma unroll
            for (int i = 0; i < 4; i++) {
                int f = tid + (i << 8);
                int row = f >> 3, c4 = (f & 7) << 2;
                cp16(Ksb[p] + SWZ32(row, c4),
                     Kb + (size_t)(p * 128 + row) * (HD/2) + c4);
            }
#pragma unroll
            for (int i = 0; i < 4; i++) {
                int f = tid + (i << 8);
                int row = f >> 3, c4 = (f & 7) << 2;
                cp16(Vsb[p] + SWZ32(row, c4),
                     Vb + (size_t)(p * 128 + row) * (HD/2) + c4);
            }
        }
        CP_COMMIT();
    }

    CP_WAIT(2);            /* Q resident */
    __syncthreads();

    /* Q fragments to registers: 4 k-steps x 4 regs (16-row A fragments) */
    uint32_t qf[4][4];
#pragma unroll
    for (int ks = 0; ks < 4; ks++) {
        const int kb = (ks << 3) + tig;
        const int row = wq + r0;
        qf[ks][0] = Qs[SWZ32(row,     kb)];
        qf[ks][1] = Qs[SWZ32(row + 8, kb)];
        qf[ks][2] = Qs[SWZ32(row,     kb + 4)];
        qf[ks][3] = Qs[SWZ32(row + 8, kb + 4)];
    }

    float o[8][4];
    float mi[2], li[2];
#pragma unroll
    for (int i = 0; i < 2; i++) { mi[i] = -1e30f; li[i] = 0.f; }
#pragma unroll
    for (int nt = 0; nt < 8; nt++)
#pragma unroll
        for (int e = 0; e < 4; e++) o[nt][e] = 0.f;

    for (int kt = 0; kt < nkt; kt++) {
        const int k0 = kt << 7;          /* 128 keys per tile */

        CP_WAIT(1);                      /* K/V[kt] resident */
        __syncthreads();

        /* prefetch K/V[kt+2] — overlaps compute below */
        if (kt + 2 < nkt) {
            const uint32_t* Kp = Kb + (size_t)(k0 + 256) * (HD/2);
            const uint32_t* Vp = Vb + (size_t)(k0 + 256) * (HD/2);
            uint32_t* Kd = Ksb[(kt + 2) % 3];
            uint32_t* Vd = Vsb[(kt + 2) % 3];
#pragma unroll
            for (int i = 0; i < 4; i++) {
                int f = tid + (i << 8);
                int row = f >> 3, c4 = (f & 7) << 2;
                cp16(Kd + SWZ32(row, c4), Kp + (size_t)row * (HD/2) + c4);
            }
#pragma unroll
            for (int i = 0; i < 4; i++) {
                int f = tid + (i << 8);
                int row = f >> 3, c4 = (f & 7) << 2;
                cp16(Vd + SWZ32(row, c4), Vp + (size_t)row * (HD/2) + c4);
            }
        }
        CP_COMMIT();                     /* always commit */

        const uint32_t kbase = (uint32_t)__cvta_generic_to_shared(Ksb[kt % 3]);
        const uint32_t vbase = (uint32_t)__cvta_generic_to_shared(Vsb[kt % 3]);

        /* S = Q K^T : 16 q-rows x 128 keys */
        float s[16][4];
#pragma unroll
        for (int nt = 0; nt < 16; nt++)
#pragma unroll
            for (int e = 0; e < 4; e++) s[nt][e] = 0.f;

#pragma unroll
        for (int ks = 0; ks < 4; ks++) {
            const int c0 = ks << 3;
            uint32_t bf[16][2];
#pragma unroll
            for (int p2 = 0; p2 < 8; p2++) {
                int n = (p2 << 4) + b_roff;
                ldsm_x4(bf[2*p2][0], bf[2*p2][1], bf[2*p2+1][0], bf[2*p2+1][1],
                        kbase + 4u * (uint32_t)SWZ32(n, c0 + b_coff));
            }
#pragma unroll
            for (int nt = 0; nt < 16; nt++)
                mma_f16(s[nt], qf[ks], bf[nt]);
        }

        /* causal mask (diagonal tile only) */
        if (k0 + 127 > q0 + wq) {
#pragma unroll
            for (int nt = 0; nt < 16; nt++)
#pragma unroll
                for (int e = 0; e < 4; e++) {
                    int rg = q0 + wq + ((e >> 1) << 3) + r0;
                    int cg = k0 + (nt << 3) + (tig << 1) + (e & 1);
                    if (cg > rg) s[nt][e] = -1e30f;
                }
        }

        /* online softmax over 128 keys (base-2); P packed to f16x2 */
        uint32_t pk[16][2];
#pragma unroll
        for (int half = 0; half < 2; half++) {
            float mx = -1e30f;
#pragma unroll
            for (int nt = 0; nt < 16; nt++)
                mx = fmaxf(mx, fmaxf(s[nt][half*2], s[nt][half*2+1]));
            mx = fmaxf(mx, __shfl_xor_sync(0xffffffffu, mx, 1));
            mx = fmaxf(mx, __shfl_xor_sync(0xffffffffu, mx, 2));
            float mnew = fmaxf(mi[half], mx);
            float corr = ex2f(mi[half] - mnew);
            uint32_t sA = 0, sB = 0;
#pragma unroll
            for (int nt = 0; nt < 16; nt++) {
                float x0 = s[nt][half*2]     - mnew;
                float x1 = s[nt][half*2 + 1] - mnew;
                uint32_t pe = ex2_h2(cvt_f16x2(x1, x0));
                pk[nt][half] = pe;
                if (nt & 1) sB = hadd2u(sB, pe); else sA = hadd2u(sA, pe);
            }
            float2 sf = __half22float2(*(__half2*)&(sA = hadd2u(sA, sB)));
            float sum = sf.x + sf.y;
            sum += __shfl_xor_sync(0xffffffffu, sum, 1);
            sum += __shfl_xor_sync(0xffffffffu, sum, 2);
            li[half] = li[half] * corr + sum;
            mi[half] = mnew;
#pragma unroll
            for (int nt = 0; nt < 8; nt++) {
                o[nt][half*2]     *= corr;
                o[nt][half*2 + 1] *= corr;
            }
        }

        /* O += P V : 8 k-steps over 128 keys */
#pragma unroll
        for (int ks = 0; ks < 8; ks++) {
            uint32_t bf[8][2];
#pragma unroll
            for (int j = 0; j < 4; j++) {
                int key = (ks << 4) + lm_key;
                int c   = ((j << 1) + lm_nt2) << 2;
                uint32_t t0, t1, t2, t3;
                asm volatile(
                    "ldmatrix.sync.aligned.m8n8.x4.trans.shared.b16 "
                    "{%0,%1,%2,%3}, [%4];"
                    : "=r"(t0), "=r"(t1), "=r"(t2), "=r"(t3)
                    : "r"(vbase + 4u * (uint32_t)SWZ32(key, c)));
                bf[(j << 1)    ][0] = t0;
                bf[(j << 1)    ][1] = t1;
                bf[(j << 1) + 1][0] = t2;
                bf[(j << 1) + 1][1] = t3;
            }
            uint32_t af[4] = { pk[2*ks][0], pk[2*ks][1],
                               pk[2*ks+1][0], pk[2*ks+1][1] };
#pragma unroll
            for (int nt = 0; nt < 8; nt++)
                mma_f16(o[nt], af, bf[nt]);
        }
    }

    /* epilogue: normalize, store packed fp16 into AO */
    const int b = bh >> 4, h = bh & 15;
#pragma unroll
    for (int half = 0; half < 2; half++) {
        const float inv = 1.f / li[half];
        const int rg = q0 + wq + (half << 3) + r0;
        uint32_t* row = AO + (size_t)(b * SEQ + rg) * GSTRIDE + (h << 5);
#pragma unroll
        for (int nt = 0; nt < 8; nt++) {
            row[(nt << 2) + tig] = h2pack(o[nt][half*2]     * inv,
                                          o[nt][half*2 + 1] * inv);
        }
    }
}

/* ---------------- launch -------------------------------------------------- */
extern "C" void kernel_launch(void* const* d_in, const int* in_sizes, int n_in,
                              void* d_out, int out_size)
{
    const float* q  = (const float*)d_in[0];
    const float* k  = (const float*)d_in[1];
    const float* v  = (const float*)d_in[2];
    const float* wq = (const float*)d_in[3];
    const float* wk = (const float*)d_in[4];
    const float* wv = (const float*)d_in[5];
    const float* wo = (const float*)d_in[6];

    uint32_t *qt, *kt, *vt, *wqt, *wkt, *wvt, *wot, *qh, *kh, *vh, *ao;
    cudaGetSymbolAddress((void**)&qt,  g_qt);
    cudaGetSymbolAddress((void**)&kt,  g_kt);
    cudaGetSymbolAddress((void**)&vt,  g_vt);
    cudaGetSymbolAddress((void**)&wqt, g_wq);
    cudaGetSymbolAddress((void**)&wkt, g_wk);
    cudaGetSymbolAddress((void**)&wvt, g_wv);
    cudaGetSymbolAddress((void**)&wot, g_wo);
    cudaGetSymbolAddress((void**)&qh,  g_qh);
    cudaGetSymbolAddress((void**)&kh,  g_kh);
    cudaGetSymbolAddress((void**)&vh,  g_vh);
    cudaGetSymbolAddress((void**)&ao,  g_ao);

    const int flash_smem = (FQ + 6 * FKV2) * 4;   /* 114688 */
    cudaFuncSetAttribute(gemm_qkv,  cudaFuncAttributeMaxDynamicSharedMemorySize, GEMM_SMEM);
    cudaFuncSetAttribute(gemm_out,  cudaFuncAttributeMaxDynamicSharedMemorySize, GEMM_SMEM);
    cudaFuncSetAttribute(flash_attn, cudaFuncAttributeMaxDynamicSharedMemorySize, flash_smem);

    dim3 gcvt(MROWS * DIM / 4 / 256, 7);     /* 4096 x 7 */
    cvt_all_kernel<<<gcvt, 256>>>(q, k, v, wq, wk, wv, wo,
                                  qt, kt, vt, wqt, wkt, wvt, wot);

    dim3 gqkv(DIM / BN, MROWS / BM, 3);        /* 8 x 32 x 3 */
    gemm_qkv<<<gqkv, 256, GEMM_SMEM>>>(qt, kt, vt, wqt, wkt, wvt, qh, kh, vh);

    flash_attn<<<dim3(SEQ / 128, BATCH * NH), 256, flash_smem>>>(qh, kh, vh, ao);

    dim3 gout(DIM / BN, MROWS / BM);           /* 8 x 32 */
    gemm_out<<<gout, 256, GEMM_SMEM>>>(ao, wot, (float*)d_out);
}